// round 15
// baseline (speedup 1.0000x reference)
#include <cuda_runtime.h>
#include <cuda_fp16.h>
#include <cstdint>

#define Bz 8
#define Ns 2048
#define Ms 2048
#define Dd 1024
#define Hh 1024
#define Oo 1024

#define BM 128
#define BN 128
#define BK 64
#define LDS 72        // padded row stride in halves (144B; conflict-free ldmatrix)
#define NSTAGE 2

// ---------------- device scratch ----------------
__device__ __half g_h1h[Bz * Ns * Dd];
__device__ __half g_h2h[Bz * Ms * Dd];
__device__ __half g_Wqh[Hh * Dd];
__device__ __half g_Wkh[Hh * Dd];
__device__ __half g_Wvh[Oo * Dd];
__device__ __half g_Qh[Bz * Ns * Hh];
__device__ __half g_Kh[Bz * Ms * Hh];
__device__ __half g_Vth[Bz * Oo * Ms];   // V transposed: [b][o][m]
__device__ __half g_P[(size_t)Bz * Ns * Ms];  // unnormalized exp weights
__device__ float  g_S[Bz * Ns];               // per-row exp sums (atomics)

// ---------------- fused fp32 -> fp16 convert (hi only, all tensors) ----------------
#define R0 4194304    // h1 float4 count
#define R1 8388608    // + h2
#define R2q 8650752   // + Wq
#define R3k 8912896   // + Wk
#define R4v 9175040   // + Wv

__global__ void split_all_kernel(const float4* __restrict__ h1, const float4* __restrict__ h2,
                                 const float4* __restrict__ Wq, const float4* __restrict__ Wk,
                                 const float4* __restrict__ Wv,
                                 __half2* __restrict__ h1h, __half2* __restrict__ h2h,
                                 __half2* __restrict__ Wqh, __half2* __restrict__ Wkh,
                                 __half2* __restrict__ Wvh) {
    int i = blockIdx.x * blockDim.x + threadIdx.x;
    const float4* src;
    __half2* hi;
    int j;
    if (i < R0)       { src = h1; hi = h1h; j = i; }
    else if (i < R1)  { src = h2; hi = h2h; j = i - R0; }
    else if (i < R2q) { src = Wq; hi = Wqh; j = i - R1; }
    else if (i < R3k) { src = Wk; hi = Wkh; j = i - R2q; }
    else if (i < R4v) { src = Wv; hi = Wvh; j = i - R3k; }
    else return;
    float4 v = src[j];
    hi[2 * j + 0] = __halves2half2(__float2half_rn(v.x), __float2half_rn(v.y));
    hi[2 * j + 1] = __halves2half2(__float2half_rn(v.z), __float2half_rn(v.w));
}

// ---------------- PTX helpers ----------------
__device__ __forceinline__ void ldsm4(uint32_t& r0, uint32_t& r1, uint32_t& r2, uint32_t& r3,
                                      uint32_t addr) {
    asm volatile("ldmatrix.sync.aligned.m8n8.x4.shared.b16 {%0,%1,%2,%3}, [%4];"
                 : "=r"(r0), "=r"(r1), "=r"(r2), "=r"(r3)
                 : "r"(addr));
}

__device__ __forceinline__ void mma16816(float* c, const uint32_t* a, uint32_t b0, uint32_t b1) {
    asm volatile("mma.sync.aligned.m16n8k16.row.col.f32.f16.f16.f32 "
                 "{%0,%1,%2,%3}, {%4,%5,%6,%7}, {%8,%9}, {%0,%1,%2,%3};"
                 : "+f"(c[0]), "+f"(c[1]), "+f"(c[2]), "+f"(c[3])
                 : "r"(a[0]), "r"(a[1]), "r"(a[2]), "r"(a[3]), "r"(b0), "r"(b1));
}

__device__ __forceinline__ void cp16(uint32_t dst, const void* src) {
    asm volatile("cp.async.cg.shared.global [%0], [%1], 16;" :: "r"(dst), "l"(src));
}
__device__ __forceinline__ void cp_commit() { asm volatile("cp.async.commit_group;"); }
template <int N>
__device__ __forceinline__ void cp_wait() { asm volatile("cp.async.wait_group %0;" :: "n"(N)); }

// ---------------- double-buffered fp16 GEMM, BK=64, 2 CTAs/SM ----------------
// C = A*B^T.  A: [Mdim x K] row-major, B: [Ndim x K] row-major (K-contiguous).
// EPI 2: fp16 C.
// EPI 3: P' = exp(mask ? C/32 : -inf) fp16  + atomic row sums into pS.
// EPI 4: fp32 C scaled by 1/pS[row].
template <int EPI>
__global__ void __launch_bounds__(256, 2)
gemm_kernel(const __half* __restrict__ pA, const __half* __restrict__ pB,
            float* __restrict__ pCf, __half* __restrict__ pCh,
            const int* __restrict__ pMask, float* __restrict__ pS,
            int Kdim, int lda, int ldb, int ldc,
            long long sA, long long sB, long long sC) {
    extern __shared__ __align__(16) __half sm[];
    constexpr int TILE = BM * LDS;                 // halves per tile (9216)
    constexpr uint32_t STAGE_B = 2 * TILE * 2;     // A, B = 36864 B

    const int tid = threadIdx.x;
    const int bz = blockIdx.z;
    const int m0 = blockIdx.y * BM;
    const int n0 = blockIdx.x * BN;

    const __half* gA = pA + (size_t)bz * sA + (size_t)m0 * lda;
    const __half* gB = pB + (size_t)bz * sB + (size_t)n0 * ldb;

    const uint32_t smbase = (uint32_t)__cvta_generic_to_shared(sm);

    const int lane = tid & 31;
    const int wid = tid >> 5;
    const int wm0 = (wid & 1) * 64;
    const int wn0 = (wid >> 1) * 32;

    const uint32_t aoff =
        (uint32_t)(((wm0 + (lane & 15)) * LDS + ((lane >> 4) & 1) * 8) * 2);
    const uint32_t boff =
        (uint32_t)(((wn0 + (lane & 7) + ((lane >> 4) & 1) * 8) * LDS + ((lane >> 3) & 1) * 8) * 2);

    float acc[4][4][4];
#pragma unroll
    for (int i = 0; i < 4; i++)
#pragma unroll
        for (int j = 0; j < 4; j++)
#pragma unroll
            for (int k = 0; k < 4; k++) acc[i][j][k] = 0.f;

    // ---- stage load (cp.async): 4 chunks per thread per tile ----
    auto issue = [&](int st, int kt) {
        const uint32_t b = smbase + (uint32_t)st * STAGE_B;
#pragma unroll
        for (int i = 0; i < 4; i++) {
            const int q = i * 256 + tid;
            const int r = q >> 3, c = (q & 7) * 8;   // row 0..127, col chunk (halves)
            const uint32_t d = b + (uint32_t)((r * LDS + c) * 2);
            cp16(d, gA + (size_t)r * lda + kt + c);
            cp16(d + TILE * 2, gB + (size_t)r * ldb + kt + c);
        }
        cp_commit();
    };

    // ---- stage compute: 4 kk steps of K=16 ----
    auto compute = [&](int st) {
        const uint32_t b = smbase + (uint32_t)st * STAGE_B;
        const uint32_t uA = b + aoff;
        const uint32_t uB = b + TILE * 2 + boff;
#pragma unroll
        for (int kk = 0; kk < 4; kk++) {
            uint32_t fA[4][4], fB[4][2];
#pragma unroll
            for (int mt = 0; mt < 4; mt++)
                ldsm4(fA[mt][0], fA[mt][1], fA[mt][2], fA[mt][3],
                      uA + mt * (16 * LDS * 2) + kk * 32);
#pragma unroll
            for (int p = 0; p < 2; p++) {
                uint32_t r0, r1, r2, r3;
                ldsm4(r0, r1, r2, r3, uB + p * (16 * LDS * 2) + kk * 32);
                fB[2 * p][0] = r0; fB[2 * p][1] = r1;
                fB[2 * p + 1][0] = r2; fB[2 * p + 1][1] = r3;
            }
#pragma unroll
            for (int mt = 0; mt < 4; mt++)
#pragma unroll
                for (int nt = 0; nt < 4; nt++)
                    mma16816(acc[mt][nt], fA[mt], fB[nt][0], fB[nt][1]);
        }
    };

    // ---- double-buffer pipeline (KT = Kdim/64) ----
    const int KT = Kdim / BK;
    issue(0, 0);
    int cur = 0;
    for (int t = 0; t < KT; t++) {
        cp_wait<0>();
        __syncthreads();
        if (t + 1 < KT) issue(1 - cur, (t + 1) * BK);
        compute(cur);
        cur ^= 1;
    }

    // ---------------- epilogue ----------------
    const int g = lane >> 2, tq = lane & 3;

    if (EPI == 2) {
#pragma unroll
        for (int mt = 0; mt < 4; mt++)
#pragma unroll
            for (int nt = 0; nt < 4; nt++) {
                const int r = m0 + wm0 + mt * 16 + g;
                const int c = n0 + wn0 + nt * 8 + tq * 2;
                __half* Ch = pCh + (size_t)bz * sC;
                *(__half2*)&Ch[(size_t)r * ldc + c] =
                    __halves2half2(__float2half_rn(acc[mt][nt][0]),
                                   __float2half_rn(acc[mt][nt][1]));
                *(__half2*)&Ch[(size_t)(r + 8) * ldc + c] =
                    __halves2half2(__float2half_rn(acc[mt][nt][2]),
                                   __float2half_rn(acc[mt][nt][3]));
            }
    } else if (EPI == 3) {
        __half* Ch = pCh + (size_t)bz * sC;
        const int* Mk = pMask + (size_t)bz * sC;
        float* S = pS + (size_t)bz * Ns;
        float rs[4][2];
#pragma unroll
        for (int mt = 0; mt < 4; mt++) { rs[mt][0] = 0.f; rs[mt][1] = 0.f; }
#pragma unroll
        for (int mt = 0; mt < 4; mt++) {
#pragma unroll
            for (int nt = 0; nt < 4; nt++) {
                const int r = m0 + wm0 + mt * 16 + g;
                const int c = n0 + wn0 + nt * 8 + tq * 2;
                int2 mk0 = *(const int2*)&Mk[(size_t)r * ldc + c];
                int2 mk1 = *(const int2*)&Mk[(size_t)(r + 8) * ldc + c];
                float e0 = mk0.x ? __expf(acc[mt][nt][0] * 0.03125f) : 0.f;
                float e1 = mk0.y ? __expf(acc[mt][nt][1] * 0.03125f) : 0.f;
                float e2 = mk1.x ? __expf(acc[mt][nt][2] * 0.03125f) : 0.f;
                float e3 = mk1.y ? __expf(acc[mt][nt][3] * 0.03125f) : 0.f;
                *(__half2*)&Ch[(size_t)r * ldc + c] =
                    __halves2half2(__float2half_rn(e0), __float2half_rn(e1));
                *(__half2*)&Ch[(size_t)(r + 8) * ldc + c] =
                    __halves2half2(__float2half_rn(e2), __float2half_rn(e3));
                rs[mt][0] += e0 + e1;
                rs[mt][1] += e2 + e3;
            }
        }
        // reduce the 4 tq lanes of each row group, then one atomic per row
#pragma unroll
        for (int mt = 0; mt < 4; mt++) {
#pragma unroll
            for (int h = 0; h < 2; h++) {
                float s = rs[mt][h];
                s += __shfl_xor_sync(0xffffffffu, s, 1);
                s += __shfl_xor_sync(0xffffffffu, s, 2);
                if (tq == 0) {
                    const int r = m0 + wm0 + mt * 16 + g + h * 8;
                    atomicAdd(&S[r], s);
                }
            }
        }
    } else {  // EPI == 4
        float* C = pCf + (size_t)bz * sC;
        const float* S = pS + (size_t)bz * Ns;
#pragma unroll
        for (int mt = 0; mt < 4; mt++) {
            const int r = m0 + wm0 + mt * 16 + g;
            const float inv0 = 1.0f / S[r];
            const float inv1 = 1.0f / S[r + 8];
#pragma unroll
            for (int nt = 0; nt < 4; nt++) {
                const int c = n0 + wn0 + nt * 8 + tq * 2;
                *(float2*)&C[(size_t)r * ldc + c] =
                    make_float2(acc[mt][nt][0] * inv0, acc[mt][nt][1] * inv0);
                *(float2*)&C[(size_t)(r + 8) * ldc + c] =
                    make_float2(acc[mt][nt][2] * inv1, acc[mt][nt][3] * inv1);
            }
        }
    }
}

// ---------------- launch ----------------
extern "C" void kernel_launch(void* const* d_in, const int* in_sizes, int n_in,
                              void* d_out, int out_size) {
    (void)in_sizes; (void)n_in; (void)out_size;
    const float* h1 = (const float*)d_in[0];
    const float* h2 = (const float*)d_in[1];
    const int* mask = (const int*)d_in[2];
    const float* Wq = (const float*)d_in[3];
    const float* Wk = (const float*)d_in[4];
    const float* Wv = (const float*)d_in[5];
    float* out = (float*)d_out;

    __half *h1h, *h2h, *Wqh, *Wkh, *Wvh;
    __half *Qh, *Kh, *Vth, *P;
    float* S;
    cudaGetSymbolAddress((void**)&h1h, g_h1h);
    cudaGetSymbolAddress((void**)&h2h, g_h2h);
    cudaGetSymbolAddress((void**)&Wqh, g_Wqh);
    cudaGetSymbolAddress((void**)&Wkh, g_Wkh);
    cudaGetSymbolAddress((void**)&Wvh, g_Wvh);
    cudaGetSymbolAddress((void**)&Qh, g_Qh);
    cudaGetSymbolAddress((void**)&Kh, g_Kh);
    cudaGetSymbolAddress((void**)&Vth, g_Vth);
    cudaGetSymbolAddress((void**)&P, g_P);
    cudaGetSymbolAddress((void**)&S, g_S);

    const int smem1 = 2 * BM * LDS * 2 * NSTAGE;   // 73728 B -> 2 CTAs/SM
    cudaFuncSetAttribute((const void*)gemm_kernel<2>,
                         cudaFuncAttributeMaxDynamicSharedMemorySize, smem1);
    cudaFuncSetAttribute((const void*)gemm_kernel<3>,
                         cudaFuncAttributeMaxDynamicSharedMemorySize, smem1);
    cudaFuncSetAttribute((const void*)gemm_kernel<4>,
                         cudaFuncAttributeMaxDynamicSharedMemorySize, smem1);

    // fused fp32->fp16 convert, single launch
    split_all_kernel<<<(R4v + 255) / 256, 256>>>(
        (const float4*)h1, (const float4*)h2, (const float4*)Wq, (const float4*)Wk,
        (const float4*)Wv,
        (__half2*)h1h, (__half2*)h2h, (__half2*)Wqh, (__half2*)Wkh, (__half2*)Wvh);

    // zero the row-sum accumulator (graph-capturable async memset)
    cudaMemsetAsync(S, 0, Bz * Ns * sizeof(float));

    // Qh = h1h * Wqh^T (16384 x 1024 x 1024), fp16 epilogue
    gemm_kernel<2><<<dim3(Hh / BN, (Bz * Ns) / BM, 1), 256, smem1>>>(
        h1h, Wqh, nullptr, Qh, nullptr, nullptr, Dd, Dd, Dd, Hh, 0, 0, 0);
    // Kh = h2h * Wkh^T, fp16 epilogue
    gemm_kernel<2><<<dim3(Hh / BN, (Bz * Ms) / BM, 1), 256, smem1>>>(
        h2h, Wkh, nullptr, Kh, nullptr, nullptr, Dd, Dd, Dd, Hh, 0, 0, 0);
    // Vth[b] = Wvh * h2h[b]^T, fp16 epilogue
    gemm_kernel<2><<<dim3(Ms / BN, Oo / BM, Bz), 256, smem1>>>(
        Wvh, h2h, nullptr, Vth, nullptr, nullptr, Dd, Dd, Dd, Ms,
        0, (long long)Ms * Dd, (long long)Oo * Ms);
    // P'[b] = exp(mask ? Qh*Kh^T/32 : -inf), rowsums -> S  (fused softmax part 1)
    gemm_kernel<3><<<dim3(Ms / BN, Ns / BM, Bz), 256, smem1>>>(
        Qh, Kh, nullptr, P, mask, S, Hh, Hh, Hh, Ms,
        (long long)Ns * Hh, (long long)Ms * Hh, (long long)Ns * Ms);
    // out[b] = (P'[b] * Vth[b]^T) / S[row]  (fused softmax part 2)
    gemm_kernel<4><<<dim3(Oo / BN, Ns / BM, Bz), 256, smem1>>>(
        P, Vth, out, nullptr, nullptr, S, Ms, Ms, Ms, Oo,
        (long long)Ns * Ms, (long long)Oo * Ms, (long long)Ns * Oo);
}

// round 16
// speedup vs baseline: 1.5129x; 1.5129x over previous
#include <cuda_runtime.h>
#include <cuda_fp16.h>
#include <cstdint>

#define Bz 8
#define Ns 2048
#define Ms 2048
#define Dd 1024
#define Hh 1024
#define Oo 1024

#define BM 128
#define BN 128
#define BK 64
#define LDS 72        // padded row stride in halves (144B; conflict-free ldmatrix)
#define NSTAGE 2

// ---------------- device scratch ----------------
__device__ __half g_h1h[Bz * Ns * Dd];
__device__ __half g_h2h[Bz * Ms * Dd];
__device__ __half g_Wqh[Hh * Dd];
__device__ __half g_Wkh[Hh * Dd];
__device__ __half g_Wvh[Oo * Dd];
__device__ __half g_Qh[Bz * Ns * Hh];
__device__ __half g_Kh[Bz * Ms * Hh];
__device__ __half g_Vth[Bz * Oo * Ms];   // V transposed: [b][o][m]
__device__ __half g_P[(size_t)Bz * Ns * Ms];  // unnormalized exp weights
__device__ float  g_S[Bz * Ns];               // per-row exp sums (atomics)

// ---------------- fused fp32 -> fp16 convert (hi only, all tensors) ----------------
#define R0 4194304    // h1 float4 count
#define R1 8388608    // + h2
#define R2q 8650752   // + Wq
#define R3k 8912896   // + Wk
#define R4v 9175040   // + Wv

__global__ void split_all_kernel(const float4* __restrict__ h1, const float4* __restrict__ h2,
                                 const float4* __restrict__ Wq, const float4* __restrict__ Wk,
                                 const float4* __restrict__ Wv,
                                 __half2* __restrict__ h1h, __half2* __restrict__ h2h,
                                 __half2* __restrict__ Wqh, __half2* __restrict__ Wkh,
                                 __half2* __restrict__ Wvh) {
    int i = blockIdx.x * blockDim.x + threadIdx.x;
    const float4* src;
    __half2* hi;
    int j;
    if (i < R0)       { src = h1; hi = h1h; j = i; }
    else if (i < R1)  { src = h2; hi = h2h; j = i - R0; }
    else if (i < R2q) { src = Wq; hi = Wqh; j = i - R1; }
    else if (i < R3k) { src = Wk; hi = Wkh; j = i - R2q; }
    else if (i < R4v) { src = Wv; hi = Wvh; j = i - R3k; }
    else return;
    float4 v = src[j];
    hi[2 * j + 0] = __halves2half2(__float2half_rn(v.x), __float2half_rn(v.y));
    hi[2 * j + 1] = __halves2half2(__float2half_rn(v.z), __float2half_rn(v.w));
}

// ---------------- PTX helpers ----------------
__device__ __forceinline__ void ldsm4(uint32_t& r0, uint32_t& r1, uint32_t& r2, uint32_t& r3,
                                      uint32_t addr) {
    asm volatile("ldmatrix.sync.aligned.m8n8.x4.shared.b16 {%0,%1,%2,%3}, [%4];"
                 : "=r"(r0), "=r"(r1), "=r"(r2), "=r"(r3)
                 : "r"(addr));
}

__device__ __forceinline__ void mma16816(float* c, const uint32_t* a, uint32_t b0, uint32_t b1) {
    asm volatile("mma.sync.aligned.m16n8k16.row.col.f32.f16.f16.f32 "
                 "{%0,%1,%2,%3}, {%4,%5,%6,%7}, {%8,%9}, {%0,%1,%2,%3};"
                 : "+f"(c[0]), "+f"(c[1]), "+f"(c[2]), "+f"(c[3])
                 : "r"(a[0]), "r"(a[1]), "r"(a[2]), "r"(a[3]), "r"(b0), "r"(b1));
}

__device__ __forceinline__ void cp16(uint32_t dst, const void* src) {
    asm volatile("cp.async.cg.shared.global [%0], [%1], 16;" :: "r"(dst), "l"(src));
}
__device__ __forceinline__ void cp_commit() { asm volatile("cp.async.commit_group;"); }
template <int N>
__device__ __forceinline__ void cp_wait() { asm volatile("cp.async.wait_group %0;" :: "n"(N)); }

// ---------------- double-buffered fp16 GEMM, BK=64, 2 CTAs/SM ----------------
// C = A*B^T.  A: [Mdim x K] row-major, B: [Ndim x K] row-major (K-contiguous).
// EPI 2: fp16 C.
// EPI 3: P' = exp(mask ? C/32 : -inf) fp16  + atomic row sums into pS.
// EPI 4: fp32 C scaled by 1/pS[row].
template <int EPI>
__global__ void __launch_bounds__(256, 2)
gemm_kernel(const __half* __restrict__ pA, const __half* __restrict__ pB,
            float* __restrict__ pCf, __half* __restrict__ pCh,
            const int* __restrict__ pMask, float* __restrict__ pS,
            int Kdim, int lda, int ldb, int ldc,
            long long sA, long long sB, long long sC) {
    extern __shared__ __align__(16) __half sm[];
    constexpr int TILE = BM * LDS;                 // halves per tile (9216)
    constexpr uint32_t STAGE_B = 2 * TILE * 2;     // A, B = 36864 B

    const int tid = threadIdx.x;
    const int bz = blockIdx.z;
    const int m0 = blockIdx.y * BM;
    const int n0 = blockIdx.x * BN;

    const __half* gA = pA + (size_t)bz * sA + (size_t)m0 * lda;
    const __half* gB = pB + (size_t)bz * sB + (size_t)n0 * ldb;

    const uint32_t smbase = (uint32_t)__cvta_generic_to_shared(sm);

    const int lane = tid & 31;
    const int wid = tid >> 5;
    const int wm0 = (wid & 1) * 64;
    const int wn0 = (wid >> 1) * 32;

    const uint32_t aoff =
        (uint32_t)(((wm0 + (lane & 15)) * LDS + ((lane >> 4) & 1) * 8) * 2);
    const uint32_t boff =
        (uint32_t)(((wn0 + (lane & 7) + ((lane >> 4) & 1) * 8) * LDS + ((lane >> 3) & 1) * 8) * 2);

    float acc[4][4][4];
#pragma unroll
    for (int i = 0; i < 4; i++)
#pragma unroll
        for (int j = 0; j < 4; j++)
#pragma unroll
            for (int k = 0; k < 4; k++) acc[i][j][k] = 0.f;

    // ---- stage load (cp.async): 4 chunks per thread per tile ----
    auto issue = [&](int st, int kt) {
        const uint32_t b = smbase + (uint32_t)st * STAGE_B;
#pragma unroll
        for (int i = 0; i < 4; i++) {
            const int q = i * 256 + tid;
            const int r = q >> 3, c = (q & 7) * 8;   // row 0..127, col chunk (halves)
            const uint32_t d = b + (uint32_t)((r * LDS + c) * 2);
            cp16(d, gA + (size_t)r * lda + kt + c);
            cp16(d + TILE * 2, gB + (size_t)r * ldb + kt + c);
        }
        cp_commit();
    };

    // ---- stage compute: 4 kk steps of K=16 ----
    auto compute = [&](int st) {
        const uint32_t b = smbase + (uint32_t)st * STAGE_B;
        const uint32_t uA = b + aoff;
        const uint32_t uB = b + TILE * 2 + boff;
#pragma unroll
        for (int kk = 0; kk < 4; kk++) {
            uint32_t fA[4][4], fB[4][2];
#pragma unroll
            for (int mt = 0; mt < 4; mt++)
                ldsm4(fA[mt][0], fA[mt][1], fA[mt][2], fA[mt][3],
                      uA + mt * (16 * LDS * 2) + kk * 32);
#pragma unroll
            for (int p = 0; p < 2; p++) {
                uint32_t r0, r1, r2, r3;
                ldsm4(r0, r1, r2, r3, uB + p * (16 * LDS * 2) + kk * 32);
                fB[2 * p][0] = r0; fB[2 * p][1] = r1;
                fB[2 * p + 1][0] = r2; fB[2 * p + 1][1] = r3;
            }
#pragma unroll
            for (int mt = 0; mt < 4; mt++)
#pragma unroll
                for (int nt = 0; nt < 4; nt++)
                    mma16816(acc[mt][nt], fA[mt], fB[nt][0], fB[nt][1]);
        }
    };

    // ---- double-buffer pipeline (KT = Kdim/64) ----
    const int KT = Kdim / BK;
    issue(0, 0);
    int cur = 0;
    for (int t = 0; t < KT; t++) {
        cp_wait<0>();
        __syncthreads();
        if (t + 1 < KT) issue(1 - cur, (t + 1) * BK);
        compute(cur);
        cur ^= 1;
    }

    // ---------------- epilogue ----------------
    const int g = lane >> 2, tq = lane & 3;

    if (EPI == 2) {
#pragma unroll
        for (int mt = 0; mt < 4; mt++)
#pragma unroll
            for (int nt = 0; nt < 4; nt++) {
                const int r = m0 + wm0 + mt * 16 + g;
                const int c = n0 + wn0 + nt * 8 + tq * 2;
                __half* Ch = pCh + (size_t)bz * sC;
                *(__half2*)&Ch[(size_t)r * ldc + c] =
                    __halves2half2(__float2half_rn(acc[mt][nt][0]),
                                   __float2half_rn(acc[mt][nt][1]));
                *(__half2*)&Ch[(size_t)(r + 8) * ldc + c] =
                    __halves2half2(__float2half_rn(acc[mt][nt][2]),
                                   __float2half_rn(acc[mt][nt][3]));
            }
    } else if (EPI == 3) {
        __half* Ch = pCh + (size_t)bz * sC;
        const int* Mk = pMask + (size_t)bz * sC;
        float* S = pS + (size_t)bz * Ns;
        float rs[4][2];
#pragma unroll
        for (int mt = 0; mt < 4; mt++) { rs[mt][0] = 0.f; rs[mt][1] = 0.f; }
#pragma unroll
        for (int mt = 0; mt < 4; mt++) {
#pragma unroll
            for (int nt = 0; nt < 4; nt++) {
                const int r = m0 + wm0 + mt * 16 + g;
                const int c = n0 + wn0 + nt * 8 + tq * 2;
                int2 mk0 = *(const int2*)&Mk[(size_t)r * ldc + c];
                int2 mk1 = *(const int2*)&Mk[(size_t)(r + 8) * ldc + c];
                float e0 = mk0.x ? __expf(acc[mt][nt][0] * 0.03125f) : 0.f;
                float e1 = mk0.y ? __expf(acc[mt][nt][1] * 0.03125f) : 0.f;
                float e2 = mk1.x ? __expf(acc[mt][nt][2] * 0.03125f) : 0.f;
                float e3 = mk1.y ? __expf(acc[mt][nt][3] * 0.03125f) : 0.f;
                *(__half2*)&Ch[(size_t)r * ldc + c] =
                    __halves2half2(__float2half_rn(e0), __float2half_rn(e1));
                *(__half2*)&Ch[(size_t)(r + 8) * ldc + c] =
                    __halves2half2(__float2half_rn(e2), __float2half_rn(e3));
                rs[mt][0] += e0 + e1;
                rs[mt][1] += e2 + e3;
            }
        }
        // reduce the 4 tq lanes of each row group, then one atomic per row
#pragma unroll
        for (int mt = 0; mt < 4; mt++) {
#pragma unroll
            for (int h = 0; h < 2; h++) {
                float s = rs[mt][h];
                s += __shfl_xor_sync(0xffffffffu, s, 1);
                s += __shfl_xor_sync(0xffffffffu, s, 2);
                if (tq == 0) {
                    const int r = m0 + wm0 + mt * 16 + g + h * 8;
                    atomicAdd(&S[r], s);
                }
            }
        }
    } else {  // EPI == 4
        float* C = pCf + (size_t)bz * sC;
        const float* S = pS + (size_t)bz * Ns;
#pragma unroll
        for (int mt = 0; mt < 4; mt++) {
            const int r = m0 + wm0 + mt * 16 + g;
            const float inv0 = 1.0f / S[r];
            const float inv1 = 1.0f / S[r + 8];
#pragma unroll
            for (int nt = 0; nt < 4; nt++) {
                const int c = n0 + wn0 + nt * 8 + tq * 2;
                *(float2*)&C[(size_t)r * ldc + c] =
                    make_float2(acc[mt][nt][0] * inv0, acc[mt][nt][1] * inv0);
                *(float2*)&C[(size_t)(r + 8) * ldc + c] =
                    make_float2(acc[mt][nt][2] * inv1, acc[mt][nt][3] * inv1);
            }
        }
    }
}

// ---------------- launch ----------------
extern "C" void kernel_launch(void* const* d_in, const int* in_sizes, int n_in,
                              void* d_out, int out_size) {
    (void)in_sizes; (void)n_in; (void)out_size;
    const float* h1 = (const float*)d_in[0];
    const float* h2 = (const float*)d_in[1];
    const int* mask = (const int*)d_in[2];
    const float* Wq = (const float*)d_in[3];
    const float* Wk = (const float*)d_in[4];
    const float* Wv = (const float*)d_in[5];
    float* out = (float*)d_out;

    __half *h1h, *h2h, *Wqh, *Wkh, *Wvh;
    __half *Qh, *Kh, *Vth, *P;
    float* S;
    cudaGetSymbolAddress((void**)&h1h, g_h1h);
    cudaGetSymbolAddress((void**)&h2h, g_h2h);
    cudaGetSymbolAddress((void**)&Wqh, g_Wqh);
    cudaGetSymbolAddress((void**)&Wkh, g_Wkh);
    cudaGetSymbolAddress((void**)&Wvh, g_Wvh);
    cudaGetSymbolAddress((void**)&Qh, g_Qh);
    cudaGetSymbolAddress((void**)&Kh, g_Kh);
    cudaGetSymbolAddress((void**)&Vth, g_Vth);
    cudaGetSymbolAddress((void**)&P, g_P);
    cudaGetSymbolAddress((void**)&S, g_S);

    const int smem1 = 2 * BM * LDS * 2 * NSTAGE;   // 73728 B -> 2 CTAs/SM
    cudaFuncSetAttribute((const void*)gemm_kernel<2>,
                         cudaFuncAttributeMaxDynamicSharedMemorySize, smem1);
    cudaFuncSetAttribute((const void*)gemm_kernel<3>,
                         cudaFuncAttributeMaxDynamicSharedMemorySize, smem1);
    cudaFuncSetAttribute((const void*)gemm_kernel<4>,
                         cudaFuncAttributeMaxDynamicSharedMemorySize, smem1);

    // zero the row-sum accumulator first (off the critical path)
    cudaMemsetAsync(S, 0, Bz * Ns * sizeof(float));

    // fused fp32->fp16 convert, single launch
    split_all_kernel<<<(R4v + 255) / 256, 256>>>(
        (const float4*)h1, (const float4*)h2, (const float4*)Wq, (const float4*)Wk,
        (const float4*)Wv,
        (__half2*)h1h, (__half2*)h2h, (__half2*)Wqh, (__half2*)Wkh, (__half2*)Wvh);

    // Qh = h1h * Wqh^T (16384 x 1024 x 1024), fp16 epilogue
    gemm_kernel<2><<<dim3(Hh / BN, (Bz * Ns) / BM, 1), 256, smem1>>>(
        h1h, Wqh, nullptr, Qh, nullptr, nullptr, Dd, Dd, Dd, Hh, 0, 0, 0);
    // Kh = h2h * Wkh^T, fp16 epilogue
    gemm_kernel<2><<<dim3(Hh / BN, (Bz * Ms) / BM, 1), 256, smem1>>>(
        h2h, Wkh, nullptr, Kh, nullptr, nullptr, Dd, Dd, Dd, Hh, 0, 0, 0);
    // Vth[b] = Wvh * h2h[b]^T, fp16 epilogue
    gemm_kernel<2><<<dim3(Ms / BN, Oo / BM, Bz), 256, smem1>>>(
        Wvh, h2h, nullptr, Vth, nullptr, nullptr, Dd, Dd, Dd, Ms,
        0, (long long)Ms * Dd, (long long)Oo * Ms);
    // P'[b] = exp(mask ? Qh*Kh^T/32 : -inf), rowsums -> S  (fused softmax part 1)
    gemm_kernel<3><<<dim3(Ms / BN, Ns / BM, Bz), 256, smem1>>>(
        Qh, Kh, nullptr, P, mask, S, Hh, Hh, Hh, Ms,
        (long long)Ns * Hh, (long long)Ms * Hh, (long long)Ns * Ms);
    // out[b] = (P'[b] * Vth[b]^T) / S[row]  (fused softmax part 2)
    gemm_kernel<4><<<dim3(Oo / BN, Ns / BM, Bz), 256, smem1>>>(
        P, Vth, out, nullptr, nullptr, S, Ms, Ms, Ms, Oo,
        (long long)Ns * Ms, (long long)Oo * Ms, (long long)Ns * Oo);
}

// round 17
// speedup vs baseline: 1.5860x; 1.0483x over previous
#include <cuda_runtime.h>
#include <cuda_fp16.h>
#include <cstdint>

#define Bz 8
#define Ns 2048
#define Ms 2048
#define Dd 1024
#define Hh 1024
#define Oo 1024

#define BM 128
#define BN 128
#define BK 64
#define LDS 72        // padded row stride in halves (144B; conflict-free ldmatrix)
#define NSTAGE 2

// ---------------- device scratch ----------------
__device__ __half g_h1h[Bz * Ns * Dd];
__device__ __half g_h2h[Bz * Ms * Dd];
__device__ __half g_Wqh[Hh * Dd];
__device__ __half g_Wkh[Hh * Dd];
__device__ __half g_Wvh[Oo * Dd];
__device__ __half g_Qh[Bz * Ns * Hh];
__device__ __half g_Kh[Bz * Ms * Hh];
__device__ __half g_Vth[Bz * Oo * Ms];   // V transposed: [b][o][m]
__device__ __half g_P[(size_t)Bz * Ns * Ms];  // unnormalized exp weights
__device__ float  g_S[Bz * Ns];               // per-row exp sums (atomics)

// ---------------- fused fp32 -> fp16 convert (hi only, all tensors) ----------------
#define R0 4194304    // h1 float4 count
#define R1 8388608    // + h2
#define R2q 8650752   // + Wq
#define R3k 8912896   // + Wk
#define R4v 9175040   // + Wv

__global__ void split_all_kernel(const float4* __restrict__ h1, const float4* __restrict__ h2,
                                 const float4* __restrict__ Wq, const float4* __restrict__ Wk,
                                 const float4* __restrict__ Wv,
                                 __half2* __restrict__ h1h, __half2* __restrict__ h2h,
                                 __half2* __restrict__ Wqh, __half2* __restrict__ Wkh,
                                 __half2* __restrict__ Wvh) {
    int i = blockIdx.x * blockDim.x + threadIdx.x;
    const float4* src;
    __half2* hi;
    int j;
    if (i < R0)       { src = h1; hi = h1h; j = i; }
    else if (i < R1)  { src = h2; hi = h2h; j = i - R0; }
    else if (i < R2q) { src = Wq; hi = Wqh; j = i - R1; }
    else if (i < R3k) { src = Wk; hi = Wkh; j = i - R2q; }
    else if (i < R4v) { src = Wv; hi = Wvh; j = i - R3k; }
    else return;
    float4 v = src[j];
    hi[2 * j + 0] = __halves2half2(__float2half_rn(v.x), __float2half_rn(v.y));
    hi[2 * j + 1] = __halves2half2(__float2half_rn(v.z), __float2half_rn(v.w));
}

// ---------------- PTX helpers ----------------
__device__ __forceinline__ void ldsm4(uint32_t& r0, uint32_t& r1, uint32_t& r2, uint32_t& r3,
                                      uint32_t addr) {
    asm volatile("ldmatrix.sync.aligned.m8n8.x4.shared.b16 {%0,%1,%2,%3}, [%4];"
                 : "=r"(r0), "=r"(r1), "=r"(r2), "=r"(r3)
                 : "r"(addr));
}

__device__ __forceinline__ void mma16816(float* c, const uint32_t* a, uint32_t b0, uint32_t b1) {
    asm volatile("mma.sync.aligned.m16n8k16.row.col.f32.f16.f16.f32 "
                 "{%0,%1,%2,%3}, {%4,%5,%6,%7}, {%8,%9}, {%0,%1,%2,%3};"
                 : "+f"(c[0]), "+f"(c[1]), "+f"(c[2]), "+f"(c[3])
                 : "r"(a[0]), "r"(a[1]), "r"(a[2]), "r"(a[3]), "r"(b0), "r"(b1));
}

__device__ __forceinline__ void cp16(uint32_t dst, const void* src) {
    asm volatile("cp.async.cg.shared.global [%0], [%1], 16;" :: "r"(dst), "l"(src));
}
__device__ __forceinline__ void cp_commit() { asm volatile("cp.async.commit_group;"); }
template <int N>
__device__ __forceinline__ void cp_wait() { asm volatile("cp.async.wait_group %0;" :: "n"(N)); }

// ================= shared GEMM mainloop (device inline) =================
// Computes acc += A_tile * B_tile^T over Kdim, both operands K-contiguous.
struct GemmCore {
    uint32_t smbase, aoff, boff;
    int tid;

    __device__ __forceinline__ void run(const __half* gA, const __half* gB,
                                        int Kdim, int lda, int ldb,
                                        float (&acc)[4][4][4]) {
        constexpr int TILE = BM * LDS;
        constexpr uint32_t STAGE_B = 2 * TILE * 2;
        auto issue = [&](int st, int kt) {
            const uint32_t b = smbase + (uint32_t)st * STAGE_B;
#pragma unroll
            for (int i = 0; i < 4; i++) {
                const int q = i * 256 + tid;
                const int r = q >> 3, c = (q & 7) * 8;
                const uint32_t d = b + (uint32_t)((r * LDS + c) * 2);
                cp16(d, gA + (size_t)r * lda + kt + c);
                cp16(d + TILE * 2, gB + (size_t)r * ldb + kt + c);
            }
            cp_commit();
        };
        auto compute = [&](int st) {
            const uint32_t b = smbase + (uint32_t)st * STAGE_B;
            const uint32_t uA = b + aoff;
            const uint32_t uB = b + TILE * 2 + boff;
#pragma unroll
            for (int kk = 0; kk < 4; kk++) {
                uint32_t fA[4][4], fB[4][2];
#pragma unroll
                for (int mt = 0; mt < 4; mt++)
                    ldsm4(fA[mt][0], fA[mt][1], fA[mt][2], fA[mt][3],
                          uA + mt * (16 * LDS * 2) + kk * 32);
#pragma unroll
                for (int p = 0; p < 2; p++) {
                    uint32_t r0, r1, r2, r3;
                    ldsm4(r0, r1, r2, r3, uB + p * (16 * LDS * 2) + kk * 32);
                    fB[2 * p][0] = r0; fB[2 * p][1] = r1;
                    fB[2 * p + 1][0] = r2; fB[2 * p + 1][1] = r3;
                }
#pragma unroll
                for (int mt = 0; mt < 4; mt++)
#pragma unroll
                    for (int nt = 0; nt < 4; nt++)
                        mma16816(acc[mt][nt], fA[mt], fB[nt][0], fB[nt][1]);
            }
        };
        const int KT = Kdim / BK;
        issue(0, 0);
        int cur = 0;
        for (int t = 0; t < KT; t++) {
            cp_wait<0>();
            __syncthreads();
            if (t + 1 < KT) issue(1 - cur, (t + 1) * BK);
            compute(cur);
            cur ^= 1;
        }
    }
};

// ---------------- fused Q/K/V projection kernel (3072 CTAs, region dispatch) ----------------
__global__ void __launch_bounds__(256, 2)
proj3_kernel(const __half* __restrict__ h1h, const __half* __restrict__ h2h,
             const __half* __restrict__ Wqh, const __half* __restrict__ Wkh,
             const __half* __restrict__ Wvh,
             __half* __restrict__ Qh, __half* __restrict__ Kh, __half* __restrict__ Vth) {
    extern __shared__ __align__(16) __half sm[];
    const int tid = threadIdx.x;
    const int lane = tid & 31;
    const int wid = tid >> 5;
    const int wm0 = (wid & 1) * 64;
    const int wn0 = (wid >> 1) * 32;

    // region dispatch (uniform per CTA)
    int id = blockIdx.x;
    const __half *pA, *pB;
    __half* pC;
    int m0, n0, ldc;
    if (id < 1024) {                   // Q: grid (8 n-tiles, 128 m-tiles)
        pA = h1h; pB = Wqh; pC = Qh;
        n0 = (id & 7) * BN; m0 = (id >> 3) * BM; ldc = Hh;
    } else if (id < 2048) {            // K
        id -= 1024;
        pA = h2h; pB = Wkh; pC = Kh;
        n0 = (id & 7) * BN; m0 = (id >> 3) * BM; ldc = Hh;
    } else {                           // V: per-batch (16 n-tiles, 8 m-tiles, 8 batch)
        id -= 2048;
        const int bz = id >> 7;
        pA = Wvh;
        pB = h2h + (size_t)bz * Ms * Dd;
        pC = Vth + (size_t)bz * Oo * Ms;
        n0 = (id & 15) * BN; m0 = ((id >> 4) & 7) * BM; ldc = Ms;
    }

    GemmCore core;
    core.smbase = (uint32_t)__cvta_generic_to_shared(sm);
    core.aoff = (uint32_t)(((wm0 + (lane & 15)) * LDS + ((lane >> 4) & 1) * 8) * 2);
    core.boff = (uint32_t)(((wn0 + (lane & 7) + ((lane >> 4) & 1) * 8) * LDS +
                           ((lane >> 3) & 1) * 8) * 2);
    core.tid = tid;

    float acc[4][4][4];
#pragma unroll
    for (int i = 0; i < 4; i++)
#pragma unroll
        for (int j = 0; j < 4; j++)
#pragma unroll
            for (int k = 0; k < 4; k++) acc[i][j][k] = 0.f;

    core.run(pA + (size_t)m0 * Dd, pB + (size_t)n0 * Dd, Dd, Dd, Dd, acc);

    const int g = lane >> 2, tq = lane & 3;
#pragma unroll
    for (int mt = 0; mt < 4; mt++)
#pragma unroll
        for (int nt = 0; nt < 4; nt++) {
            const int r = m0 + wm0 + mt * 16 + g;
            const int c = n0 + wn0 + nt * 8 + tq * 2;
            *(__half2*)&pC[(size_t)r * ldc + c] =
                __halves2half2(__float2half_rn(acc[mt][nt][0]),
                               __float2half_rn(acc[mt][nt][1]));
            *(__half2*)&pC[(size_t)(r + 8) * ldc + c] =
                __halves2half2(__float2half_rn(acc[mt][nt][2]),
                               __float2half_rn(acc[mt][nt][3]));
        }
}

// ---------------- E kernel: P' = exp(mask ? Q*K^T/32 : -inf), rowsums -> S ----------------
__global__ void __launch_bounds__(256, 2)
e_kernel(const __half* __restrict__ Qh, const __half* __restrict__ Kh,
         __half* __restrict__ P, const int* __restrict__ mask, float* __restrict__ S) {
    extern __shared__ __align__(16) __half sm[];
    const int tid = threadIdx.x;
    const int lane = tid & 31;
    const int wid = tid >> 5;
    const int wm0 = (wid & 1) * 64;
    const int wn0 = (wid >> 1) * 32;
    const int bz = blockIdx.z;
    const int m0 = blockIdx.y * BM;
    const int n0 = blockIdx.x * BN;

    GemmCore core;
    core.smbase = (uint32_t)__cvta_generic_to_shared(sm);
    core.aoff = (uint32_t)(((wm0 + (lane & 15)) * LDS + ((lane >> 4) & 1) * 8) * 2);
    core.boff = (uint32_t)(((wn0 + (lane & 7) + ((lane >> 4) & 1) * 8) * LDS +
                           ((lane >> 3) & 1) * 8) * 2);
    core.tid = tid;

    float acc[4][4][4];
#pragma unroll
    for (int i = 0; i < 4; i++)
#pragma unroll
        for (int j = 0; j < 4; j++)
#pragma unroll
            for (int k = 0; k < 4; k++) acc[i][j][k] = 0.f;

    core.run(Qh + (size_t)bz * Ns * Hh + (size_t)m0 * Hh,
             Kh + (size_t)bz * Ms * Hh + (size_t)n0 * Hh, Hh, Hh, Hh, acc);

    const int g = lane >> 2, tq = lane & 3;
    __half* Ch = P + (size_t)bz * Ns * Ms;
    const int* Mk = mask + (size_t)bz * Ns * Ms;
    float* Sb = S + (size_t)bz * Ns;
    float rs[4][2];
#pragma unroll
    for (int mt = 0; mt < 4; mt++) { rs[mt][0] = 0.f; rs[mt][1] = 0.f; }
#pragma unroll
    for (int mt = 0; mt < 4; mt++) {
#pragma unroll
        for (int nt = 0; nt < 4; nt++) {
            const int r = m0 + wm0 + mt * 16 + g;
            const int c = n0 + wn0 + nt * 8 + tq * 2;
            int2 mk0 = *(const int2*)&Mk[(size_t)r * Ms + c];
            int2 mk1 = *(const int2*)&Mk[(size_t)(r + 8) * Ms + c];
            float e0 = mk0.x ? __expf(acc[mt][nt][0] * 0.03125f) : 0.f;
            float e1 = mk0.y ? __expf(acc[mt][nt][1] * 0.03125f) : 0.f;
            float e2 = mk1.x ? __expf(acc[mt][nt][2] * 0.03125f) : 0.f;
            float e3 = mk1.y ? __expf(acc[mt][nt][3] * 0.03125f) : 0.f;
            *(__half2*)&Ch[(size_t)r * Ms + c] =
                __halves2half2(__float2half_rn(e0), __float2half_rn(e1));
            *(__half2*)&Ch[(size_t)(r + 8) * Ms + c] =
                __halves2half2(__float2half_rn(e2), __float2half_rn(e3));
            rs[mt][0] += e0 + e1;
            rs[mt][1] += e2 + e3;
        }
    }
#pragma unroll
    for (int mt = 0; mt < 4; mt++) {
#pragma unroll
        for (int h = 0; h < 2; h++) {
            float s = rs[mt][h];
            s += __shfl_xor_sync(0xffffffffu, s, 1);
            s += __shfl_xor_sync(0xffffffffu, s, 2);
            if (tq == 0) {
                const int r = m0 + wm0 + mt * 16 + g + h * 8;
                atomicAdd(&Sb[r], s);
            }
        }
    }
}

// ---------------- AV kernel: out = (P' * Vt^T) / S[row] ----------------
__global__ void __launch_bounds__(256, 2)
av_kernel(const __half* __restrict__ P, const __half* __restrict__ Vth,
          float* __restrict__ out, const float* __restrict__ S) {
    extern __shared__ __align__(16) __half sm[];
    const int tid = threadIdx.x;
    const int lane = tid & 31;
    const int wid = tid >> 5;
    const int wm0 = (wid & 1) * 64;
    const int wn0 = (wid >> 1) * 32;
    const int bz = blockIdx.z;
    const int m0 = blockIdx.y * BM;
    const int n0 = blockIdx.x * BN;

    GemmCore core;
    core.smbase = (uint32_t)__cvta_generic_to_shared(sm);
    core.aoff = (uint32_t)(((wm0 + (lane & 15)) * LDS + ((lane >> 4) & 1) * 8) * 2);
    core.boff = (uint32_t)(((wn0 + (lane & 7) + ((lane >> 4) & 1) * 8) * LDS +
                           ((lane >> 3) & 1) * 8) * 2);
    core.tid = tid;

    float acc[4][4][4];
#pragma unroll
    for (int i = 0; i < 4; i++)
#pragma unroll
        for (int j = 0; j < 4; j++)
#pragma unroll
            for (int k = 0; k < 4; k++) acc[i][j][k] = 0.f;

    core.run(P + (size_t)bz * Ns * Ms + (size_t)m0 * Ms,
             Vth + (size_t)bz * Oo * Ms + (size_t)n0 * Ms, Ms, Ms, Ms, acc);

    const int g = lane >> 2, tq = lane & 3;
    float* C = out + (size_t)bz * Ns * Oo;
    const float* Sb = S + (size_t)bz * Ns;
#pragma unroll
    for (int mt = 0; mt < 4; mt++) {
        const int r = m0 + wm0 + mt * 16 + g;
        const float inv0 = 1.0f / Sb[r];
        const float inv1 = 1.0f / Sb[r + 8];
#pragma unroll
        for (int nt = 0; nt < 4; nt++) {
            const int c = n0 + wn0 + nt * 8 + tq * 2;
            *(float2*)&C[(size_t)r * Oo + c] =
                make_float2(acc[mt][nt][0] * inv0, acc[mt][nt][1] * inv0);
            *(float2*)&C[(size_t)(r + 8) * Oo + c] =
                make_float2(acc[mt][nt][2] * inv1, acc[mt][nt][3] * inv1);
        }
    }
}

// ---------------- launch ----------------
extern "C" void kernel_launch(void* const* d_in, const int* in_sizes, int n_in,
                              void* d_out, int out_size) {
    (void)in_sizes; (void)n_in; (void)out_size;
    const float* h1 = (const float*)d_in[0];
    const float* h2 = (const float*)d_in[1];
    const int* mask = (const int*)d_in[2];
    const float* Wq = (const float*)d_in[3];
    const float* Wk = (const float*)d_in[4];
    const float* Wv = (const float*)d_in[5];
    float* out = (float*)d_out;

    __half *h1h, *h2h, *Wqh, *Wkh, *Wvh;
    __half *Qh, *Kh, *Vth, *P;
    float* S;
    cudaGetSymbolAddress((void**)&h1h, g_h1h);
    cudaGetSymbolAddress((void**)&h2h, g_h2h);
    cudaGetSymbolAddress((void**)&Wqh, g_Wqh);
    cudaGetSymbolAddress((void**)&Wkh, g_Wkh);
    cudaGetSymbolAddress((void**)&Wvh, g_Wvh);
    cudaGetSymbolAddress((void**)&Qh, g_Qh);
    cudaGetSymbolAddress((void**)&Kh, g_Kh);
    cudaGetSymbolAddress((void**)&Vth, g_Vth);
    cudaGetSymbolAddress((void**)&P, g_P);
    cudaGetSymbolAddress((void**)&S, g_S);

    const int smem1 = 2 * BM * LDS * 2 * NSTAGE;   // 73728 B -> 2 CTAs/SM
    cudaFuncSetAttribute((const void*)proj3_kernel,
                         cudaFuncAttributeMaxDynamicSharedMemorySize, smem1);
    cudaFuncSetAttribute((const void*)e_kernel,
                         cudaFuncAttributeMaxDynamicSharedMemorySize, smem1);
    cudaFuncSetAttribute((const void*)av_kernel,
                         cudaFuncAttributeMaxDynamicSharedMemorySize, smem1);

    // zero the row-sum accumulator first (off the critical path)
    cudaMemsetAsync(S, 0, Bz * Ns * sizeof(float));

    // fused fp32->fp16 convert, single launch
    split_all_kernel<<<(R4v + 255) / 256, 256>>>(
        (const float4*)h1, (const float4*)h2, (const float4*)Wq, (const float4*)Wk,
        (const float4*)Wv,
        (__half2*)h1h, (__half2*)h2h, (__half2*)Wqh, (__half2*)Wkh, (__half2*)Wvh);

    // fused Q/K/V projections: 3072 CTAs, one launch
    proj3_kernel<<<3072, 256, smem1>>>(h1h, h2h, Wqh, Wkh, Wvh, Qh, Kh, Vth);

    // P'[b] = exp(mask ? Qh*Kh^T/32 : -inf), rowsums -> S
    e_kernel<<<dim3(Ms / BN, Ns / BM, Bz), 256, smem1>>>(Qh, Kh, P, mask, S);

    // out[b] = (P'[b] * Vth[b]^T) / S[row]
    av_kernel<<<dim3(Oo / BN, Ns / BM, Bz), 256, smem1>>>(P, Vth, out, S);
}